// round 3
// baseline (speedup 1.0000x reference)
#include <cuda_runtime.h>
#include <cstdint>

#define NN 100000
#define NE 1600000
#define NCH 64
#define EPS 1e-5f
#define SCAN_BLK 1024
#define NB1 ((NN + SCAN_BLK - 1) / SCAN_BLK)   // 98
#define SBLK 200                               // stat partial blocks

// ---------------- scratch (device globals; no allocation allowed) ----------
__device__ int   g_deg[NN];
__device__ float g_dinv[NN];
__device__ int   g_off[NN + 1];
__device__ int   g_cur[NN];
__device__ int   g_bsum[NB1];
__device__ int2  g_csr[NE];                    // {src, w bits}
__device__ float g_Tx1[(size_t)NN * NCH];
__device__ float g_Tx2[(size_t)NN * NCH];
__device__ float g_H[(size_t)NN * NCH];
__device__ float g_Y[(size_t)NN * NCH];
__device__ float g_part[2 * SBLK * NCH];
__device__ float g_stats[2 * NCH];

// ---------------- degree ---------------------------------------------------
__global__ void k_zero_deg() {
    int i = blockIdx.x * blockDim.x + threadIdx.x;
    if (i < NN) g_deg[i] = 0;
}

// edge_index is int32 (JAX default x64-disabled demotes int64 -> int32)
__global__ void k_deg(const int* __restrict__ ei) {
    int e = blockIdx.x * blockDim.x + threadIdx.x;
    if (e < NE) {
        int d = ei[NE + e];
        if ((unsigned)d < NN) atomicAdd(&g_deg[d], 1);
    }
}

__global__ void k_dinv() {
    int i = blockIdx.x * blockDim.x + threadIdx.x;
    if (i < NN) {
        int d = g_deg[i];
        g_dinv[i] = (d > 0) ? rsqrtf((float)d) : 0.0f;
    }
}

// ---------------- prefix sum (3-phase) -------------------------------------
__global__ void k_scan1() {
    __shared__ int sh[SCAN_BLK];
    int tid = threadIdx.x;
    int i = blockIdx.x * SCAN_BLK + tid;
    int v = (i < NN) ? g_deg[i] : 0;
    sh[tid] = v;
    __syncthreads();
    for (int ofs = 1; ofs < SCAN_BLK; ofs <<= 1) {
        int t = (tid >= ofs) ? sh[tid - ofs] : 0;
        __syncthreads();
        sh[tid] += t;
        __syncthreads();
    }
    if (i < NN) g_off[i + 1] = sh[tid];       // local inclusive
    if (tid == SCAN_BLK - 1) g_bsum[blockIdx.x] = sh[tid];
}

__global__ void k_scan2() {
    if (threadIdx.x == 0 && blockIdx.x == 0) {
        int a = 0;
        for (int b = 0; b < NB1; b++) { int t = g_bsum[b]; g_bsum[b] = a; a += t; }
    }
}

__global__ void k_scan3() {
    int i = blockIdx.x * blockDim.x + threadIdx.x;
    if (i < NN) g_off[i + 1] += g_bsum[i / SCAN_BLK];
    if (i == 0) g_off[0] = 0;
}

__global__ void k_curinit() {
    int i = blockIdx.x * blockDim.x + threadIdx.x;
    if (i < NN) g_cur[i] = g_off[i];
}

// ---------------- counting-sort edges into CSR by dst ----------------------
__global__ void k_fill(const int* __restrict__ ei) {
    int e = blockIdx.x * blockDim.x + threadIdx.x;
    if (e < NE) {
        int s = ei[e];
        int d = ei[NE + e];
        if ((unsigned)s < NN && (unsigned)d < NN) {
            float w = -g_dinv[s] * g_dinv[d];
            int pos = atomicAdd(&g_cur[d], 1);
            if ((unsigned)pos < NE)
                g_csr[pos] = make_int2(s, __float_as_int(w));
        }
    }
}

// ---------------- sparse propagation: one warp per dst node ----------------
// MODE 0: h=xp,    o=g_Tx1, no sub
// MODE 1: h=g_Tx1, o=g_Tx2, sub=xp      (Tx2 = 2*prop(Tx1) - x)
// MODE 2: h=g_H,   o=g_Tx1, no sub
// MODE 3: h=g_Tx1, o=g_Tx2, sub=g_H
template <int MODE>
__global__ void k_prop(const float* __restrict__ xp) {
    const float* h;
    float* o;
    const float* sub = nullptr;
    if (MODE == 0) { h = xp;    o = g_Tx1; }
    if (MODE == 1) { h = g_Tx1; o = g_Tx2; sub = xp; }
    if (MODE == 2) { h = g_H;   o = g_Tx1; }
    if (MODE == 3) { h = g_Tx1; o = g_Tx2; sub = g_H; }

    int node = blockIdx.x * (blockDim.x >> 5) + (threadIdx.x >> 5);
    if (node >= NN) return;
    int lane = threadIdx.x & 31;
    int beg = g_off[node], end = g_off[node + 1];

    float2 a0 = make_float2(0.f, 0.f);
    float2 a1 = make_float2(0.f, 0.f);
    int j = beg;
    for (; j + 3 < end; j += 4) {
        int2 e0 = g_csr[j];
        int2 e1 = g_csr[j + 1];
        int2 e2 = g_csr[j + 2];
        int2 e3 = g_csr[j + 3];
        float2 v0 = *(const float2*)(h + (size_t)e0.x * NCH + 2 * lane);
        float2 v1 = *(const float2*)(h + (size_t)e1.x * NCH + 2 * lane);
        float2 v2 = *(const float2*)(h + (size_t)e2.x * NCH + 2 * lane);
        float2 v3 = *(const float2*)(h + (size_t)e3.x * NCH + 2 * lane);
        float w0 = __int_as_float(e0.y), w1 = __int_as_float(e1.y);
        float w2 = __int_as_float(e2.y), w3 = __int_as_float(e3.y);
        a0.x += w0 * v0.x; a0.y += w0 * v0.y;
        a1.x += w1 * v1.x; a1.y += w1 * v1.y;
        a0.x += w2 * v2.x; a0.y += w2 * v2.y;
        a1.x += w3 * v3.x; a1.y += w3 * v3.y;
    }
    for (; j < end; j++) {
        int2 e0 = g_csr[j];
        float2 v0 = *(const float2*)(h + (size_t)e0.x * NCH + 2 * lane);
        float w0 = __int_as_float(e0.y);
        a0.x += w0 * v0.x; a0.y += w0 * v0.y;
    }
    float2 acc = make_float2(a0.x + a1.x, a0.y + a1.y);
    float2 r;
    if (MODE == 1 || MODE == 3) {
        float2 s = *(const float2*)(sub + (size_t)node * NCH + 2 * lane);
        r.x = 2.0f * acc.x - s.x;
        r.y = 2.0f * acc.y - s.y;
    } else {
        r = acc;
    }
    *(float2*)(o + (size_t)node * NCH + 2 * lane) = r;
}

// ---------------- ChebConv combine GEMM ------------------------------------
// Y = relu([A0|Tx1|Tx2] @ W + b), W:[192,64]. Tiled: M=128, N=64, K=192 (6x32).
// 256 threads; thread t: cols c0=(t&7)*8..+7, nodes ng=(t>>3)*4..+3.
// Static smem: swt 32x64 (8KB) + sxt 32x133 (17KB).
template <int LAYER>
__global__ void __launch_bounds__(256)
k_gemm(const float* __restrict__ xp, const float* __restrict__ W,
       const float* __restrict__ bias) {
    __shared__ float swt[32 * 64];
    __shared__ float sxt[32 * 133];

    const float* A0 = (LAYER == 0) ? xp : g_H;
    int t = threadIdx.x;
    int nbase = blockIdx.x * 128;
    int c0 = (t & 7) * 8;
    int ng = t >> 3;              // 0..31

    float acc[4][8];
#pragma unroll
    for (int q = 0; q < 8; q++) {
        float b = __ldg(&bias[c0 + q]);
#pragma unroll
        for (int i = 0; i < 4; i++) acc[i][q] = b;
    }

#pragma unroll 1
    for (int chunk = 0; chunk < 6; chunk++) {
        int term = chunk >> 1;
        int ch0 = (chunk & 1) * 32;
        const float* A = (term == 0) ? A0 : ((term == 1) ? g_Tx1 : g_Tx2);

        // W tile: rows chunk*32 .. +31
#pragma unroll
        for (int i = t; i < 512; i += 256) {
            int r = i >> 4, qc = (i & 15) * 4;
            *(float4*)&swt[r * 64 + qc] =
                *(const float4*)&W[(chunk * 32 + r) * 64 + qc];
        }
        // X tile transposed: sxt[k][nn], pad 133
#pragma unroll
        for (int i = t; i < 1024; i += 256) {
            int nn = i >> 3, q = i & 7;
            int node = nbase + nn;
            float4 v = make_float4(0.f, 0.f, 0.f, 0.f);
            if (node < NN)
                v = *(const float4*)&A[(size_t)node * NCH + ch0 + q * 4];
            sxt[(q * 4 + 0) * 133 + nn] = v.x;
            sxt[(q * 4 + 1) * 133 + nn] = v.y;
            sxt[(q * 4 + 2) * 133 + nn] = v.z;
            sxt[(q * 4 + 3) * 133 + nn] = v.w;
        }
        __syncthreads();

#pragma unroll
        for (int r = 0; r < 32; r++) {
            float4 wA = *(const float4*)&swt[r * 64 + c0];
            float4 wB = *(const float4*)&swt[r * 64 + c0 + 4];
#pragma unroll
            for (int i = 0; i < 4; i++) {
                float x = sxt[r * 133 + ng * 4 + i];
                acc[i][0] += x * wA.x; acc[i][1] += x * wA.y;
                acc[i][2] += x * wA.z; acc[i][3] += x * wA.w;
                acc[i][4] += x * wB.x; acc[i][5] += x * wB.y;
                acc[i][6] += x * wB.z; acc[i][7] += x * wB.w;
            }
        }
        __syncthreads();
    }

#pragma unroll
    for (int i = 0; i < 4; i++) {
        int node = nbase + ng * 4 + i;
        if (node < NN) {
            float4 oA, oB;
            oA.x = fmaxf(acc[i][0], 0.f); oA.y = fmaxf(acc[i][1], 0.f);
            oA.z = fmaxf(acc[i][2], 0.f); oA.w = fmaxf(acc[i][3], 0.f);
            oB.x = fmaxf(acc[i][4], 0.f); oB.y = fmaxf(acc[i][5], 0.f);
            oB.z = fmaxf(acc[i][6], 0.f); oB.w = fmaxf(acc[i][7], 0.f);
            *(float4*)&g_Y[(size_t)node * NCH + c0] = oA;
            *(float4*)&g_Y[(size_t)node * NCH + c0 + 4] = oB;
        }
    }
}

// ---------------- InstanceNorm: deterministic two-level reduction ----------
__global__ void k_stats1() {
    int c = threadIdx.x & 63;
    int r = threadIdx.x >> 6;   // 0..3
    float s = 0.f, ss = 0.f;
    for (int node = blockIdx.x * 4 + r; node < NN; node += SBLK * 4) {
        float v = g_Y[(size_t)node * NCH + c];
        s += v; ss += v * v;
    }
    __shared__ float sh[2][256];
    sh[0][threadIdx.x] = s;
    sh[1][threadIdx.x] = ss;
    __syncthreads();
    if (threadIdx.x < 64) {
        float S  = sh[0][c] + sh[0][c + 64] + sh[0][c + 128] + sh[0][c + 192];
        float SS = sh[1][c] + sh[1][c + 64] + sh[1][c + 128] + sh[1][c + 192];
        g_part[blockIdx.x * 64 + c] = S;
        g_part[(SBLK + blockIdx.x) * 64 + c] = SS;
    }
}

__global__ void k_stats2() {
    int c = threadIdx.x;
    if (c < 64) {
        float S = 0.f, SS = 0.f;
        for (int b = 0; b < SBLK; b++) {
            S += g_part[b * 64 + c];
            SS += g_part[(SBLK + b) * 64 + c];
        }
        float m = S / (float)NN;
        float var = SS / (float)NN - m * m;
        g_stats[c] = m;
        g_stats[64 + c] = rsqrtf(var + EPS);
    }
}

// LAYER 0: write g_H; LAYER 1: write outp
template <int LAYER>
__global__ void k_norm(float* __restrict__ outp) {
    float* O = (LAYER == 0) ? g_H : outp;
    __shared__ float sm_m[64], sm_r[64];
    if (threadIdx.x < 64) {
        sm_m[threadIdx.x] = g_stats[threadIdx.x];
        sm_r[threadIdx.x] = g_stats[64 + threadIdx.x];
    }
    __syncthreads();
    int i = blockIdx.x * blockDim.x + threadIdx.x;   // over float4 elements
    int total = NN * (NCH / 4);
    if (i < total) {
        float4 v = ((const float4*)g_Y)[i];
        int q = (i & 15) * 4;
        float4 o;
        o.x = (v.x - sm_m[q + 0]) * sm_r[q + 0];
        o.y = (v.y - sm_m[q + 1]) * sm_r[q + 1];
        o.z = (v.z - sm_m[q + 2]) * sm_r[q + 2];
        o.w = (v.w - sm_m[q + 3]) * sm_r[q + 3];
        ((float4*)O)[i] = o;
    }
}

// ---------------- launch (kernel launches ONLY — no other CUDA APIs) -------
extern "C" void kernel_launch(void* const* d_in, const int* in_sizes, int n_in,
                              void* d_out, int out_size) {
    const float* x        = (const float*)d_in[0];
    const int* ei         = (const int*)d_in[1];
    const float* W1       = (const float*)d_in[2];
    const float* b1       = (const float*)d_in[3];
    const float* W2       = (const float*)d_in[4];
    const float* b2       = (const float*)d_in[5];
    float* out            = (float*)d_out;

    const int TB = 256;
    int nodeBlocks = (NN + TB - 1) / TB;
    int edgeBlocks = (NE + TB - 1) / TB;
    int propBlocks = (NN + 7) / 8;            // 8 warps/block, 1 node/warp
    int gemmBlocks = (NN + 127) / 128;
    int normBlocks = (NN * 16 + TB - 1) / TB;

    // ----- graph structure build (per launch) -----
    k_zero_deg<<<nodeBlocks, TB>>>();
    k_deg<<<edgeBlocks, TB>>>(ei);
    k_dinv<<<nodeBlocks, TB>>>();
    k_scan1<<<NB1, SCAN_BLK>>>();
    k_scan2<<<1, 32>>>();
    k_scan3<<<(NN + TB - 1) / TB, TB>>>();
    k_curinit<<<nodeBlocks, TB>>>();
    k_fill<<<edgeBlocks, TB>>>(ei);

    // ----- layer 1 -----
    k_prop<0><<<propBlocks, TB>>>(x);
    k_prop<1><<<propBlocks, TB>>>(x);
    k_gemm<0><<<gemmBlocks, 256>>>(x, W1, b1);
    k_stats1<<<SBLK, 256>>>();
    k_stats2<<<1, 64>>>();
    k_norm<0><<<normBlocks, TB>>>(out);

    // ----- layer 2 -----
    k_prop<2><<<propBlocks, TB>>>(x);
    k_prop<3><<<propBlocks, TB>>>(x);
    k_gemm<1><<<gemmBlocks, 256>>>(x, W2, b2);
    k_stats1<<<SBLK, 256>>>();
    k_stats2<<<1, 64>>>();
    k_norm<1><<<normBlocks, TB>>>(out);
}

// round 4
// speedup vs baseline: 1.3719x; 1.3719x over previous
#include <cuda_runtime.h>
#include <cstdint>

#define NN 100000
#define NE 1600000
#define NCH 64
#define EPS 1e-5f
#define SCAN_BLK 1024
#define NB1 ((NN + SCAN_BLK - 1) / SCAN_BLK)   // 98
#define SBLK 200                               // stat partial blocks

// ---------------- scratch (device globals; no allocation allowed) ----------
__device__ int   g_deg[NN];
__device__ float g_dinv[NN];
__device__ int   g_off[NN + 1];
__device__ int   g_cur[NN];
__device__ int   g_bsum[NB1];
__device__ int2  g_csr[NE];                    // {src, w bits}
__device__ float g_Tx1[(size_t)NN * NCH];
__device__ float g_Tx2[(size_t)NN * NCH];
__device__ float g_H[(size_t)NN * NCH];
__device__ float g_Y[(size_t)NN * NCH];
__device__ float g_part[2 * SBLK * NCH];
__device__ float g_stats[2 * NCH];

// ---------------- degree ---------------------------------------------------
__global__ void k_zero_deg() {
    int i = blockIdx.x * blockDim.x + threadIdx.x;
    if (i < NN) g_deg[i] = 0;
}

// edge_index is int32 (JAX default x64-disabled demotes int64 -> int32)
__global__ void k_deg(const int* __restrict__ ei) {
    int e = blockIdx.x * blockDim.x + threadIdx.x;
    if (e < NE) {
        int d = ei[NE + e];
        if ((unsigned)d < NN) atomicAdd(&g_deg[d], 1);
    }
}

__global__ void k_dinv() {
    int i = blockIdx.x * blockDim.x + threadIdx.x;
    if (i < NN) {
        int d = g_deg[i];
        g_dinv[i] = (d > 0) ? rsqrtf((float)d) : 0.0f;
    }
}

// ---------------- prefix sum (3-phase) -------------------------------------
__global__ void k_scan1() {
    __shared__ int sh[SCAN_BLK];
    int tid = threadIdx.x;
    int i = blockIdx.x * SCAN_BLK + tid;
    int v = (i < NN) ? g_deg[i] : 0;
    sh[tid] = v;
    __syncthreads();
    for (int ofs = 1; ofs < SCAN_BLK; ofs <<= 1) {
        int t = (tid >= ofs) ? sh[tid - ofs] : 0;
        __syncthreads();
        sh[tid] += t;
        __syncthreads();
    }
    if (i < NN) g_off[i + 1] = sh[tid];       // local inclusive
    if (tid == SCAN_BLK - 1) g_bsum[blockIdx.x] = sh[tid];
}

__global__ void k_scan2() {
    if (threadIdx.x == 0 && blockIdx.x == 0) {
        int a = 0;
        for (int b = 0; b < NB1; b++) { int t = g_bsum[b]; g_bsum[b] = a; a += t; }
    }
}

__global__ void k_scan3() {
    int i = blockIdx.x * blockDim.x + threadIdx.x;
    if (i < NN) g_off[i + 1] += g_bsum[i / SCAN_BLK];
    if (i == 0) g_off[0] = 0;
}

__global__ void k_curinit() {
    int i = blockIdx.x * blockDim.x + threadIdx.x;
    if (i < NN) g_cur[i] = g_off[i];
}

// ---------------- counting-sort edges into CSR by dst ----------------------
__global__ void k_fill(const int* __restrict__ ei) {
    int e = blockIdx.x * blockDim.x + threadIdx.x;
    if (e < NE) {
        int s = ei[e];
        int d = ei[NE + e];
        if ((unsigned)s < NN && (unsigned)d < NN) {
            float w = -g_dinv[s] * g_dinv[d];
            int pos = atomicAdd(&g_cur[d], 1);
            if ((unsigned)pos < NE)
                g_csr[pos] = make_int2(s, __float_as_int(w));
        }
    }
}

// ---------------- sparse propagation: one warp per dst node ----------------
// Half-warp per edge: lanes 0-15 take edge j, lanes 16-31 take edge j+1.
// Each lane covers 16B of the 256B row (float4). Combine halves via shfl.
// MODE 0: h=xp,    o=g_Tx1            MODE 1: h=g_Tx1, o=g_Tx2, sub=xp
// MODE 2: h=g_H,   o=g_Tx1            MODE 3: h=g_Tx1, o=g_Tx2, sub=g_H
template <int MODE>
__global__ void k_prop(const float* __restrict__ xp) {
    const float* h;
    float* o;
    const float* sub = nullptr;
    if (MODE == 0) { h = xp;    o = g_Tx1; }
    if (MODE == 1) { h = g_Tx1; o = g_Tx2; sub = xp; }
    if (MODE == 2) { h = g_H;   o = g_Tx1; }
    if (MODE == 3) { h = g_Tx1; o = g_Tx2; sub = g_H; }

    int node = blockIdx.x * (blockDim.x >> 5) + (threadIdx.x >> 5);
    if (node >= NN) return;
    int lane = threadIdx.x & 31;
    int half = lane >> 4;           // 0 or 1
    int q4 = (lane & 15) * 4;       // column offset (floats)
    int beg = g_off[node], end = g_off[node + 1];

    float4 acc = make_float4(0.f, 0.f, 0.f, 0.f);
    int j = beg;
    // 4 edges per iteration (2 per half-warp)
    for (; j + 3 < end; j += 4) {
        int2 ea = g_csr[j + half];
        int2 eb = g_csr[j + 2 + half];
        const float4 va = *(const float4*)(h + (size_t)ea.x * NCH + q4);
        const float4 vb = *(const float4*)(h + (size_t)eb.x * NCH + q4);
        float wa = __int_as_float(ea.y), wb = __int_as_float(eb.y);
        acc.x += wa * va.x + wb * vb.x;
        acc.y += wa * va.y + wb * vb.y;
        acc.z += wa * va.z + wb * vb.z;
        acc.w += wa * va.w + wb * vb.w;
    }
    // remainder (0..3 edges), 2 at a time with predication
    for (; j < end; j += 2) {
        int jj = j + half;
        int s = 0; float w = 0.f;
        if (jj < end) { int2 e = g_csr[jj]; s = e.x; w = __int_as_float(e.y); }
        const float4 v = *(const float4*)(h + (size_t)s * NCH + q4);
        acc.x += w * v.x; acc.y += w * v.y;
        acc.z += w * v.z; acc.w += w * v.w;
    }
    // combine the two halves
    acc.x += __shfl_xor_sync(0xffffffffu, acc.x, 16);
    acc.y += __shfl_xor_sync(0xffffffffu, acc.y, 16);
    acc.z += __shfl_xor_sync(0xffffffffu, acc.z, 16);
    acc.w += __shfl_xor_sync(0xffffffffu, acc.w, 16);

    if (half == 0) {
        float4 r;
        if (MODE == 1 || MODE == 3) {
            float4 s = *(const float4*)(sub + (size_t)node * NCH + q4);
            r.x = 2.0f * acc.x - s.x;
            r.y = 2.0f * acc.y - s.y;
            r.z = 2.0f * acc.z - s.z;
            r.w = 2.0f * acc.w - s.w;
        } else {
            r = acc;
        }
        *(float4*)(o + (size_t)node * NCH + q4) = r;
    }
}

// ---------------- tf32 helpers ---------------------------------------------
__device__ __forceinline__ uint32_t f2tf(float x) {
    uint32_t r;
    asm("cvt.rna.tf32.f32 %0, %1;" : "=r"(r) : "f"(x));
    return r;
}

__device__ __forceinline__ void mma_tf32(float* c, uint32_t a0, uint32_t a1,
                                         uint32_t a2, uint32_t a3,
                                         uint32_t b0, uint32_t b1) {
    asm volatile(
        "mma.sync.aligned.m16n8k8.row.col.f32.tf32.tf32.f32 "
        "{%0,%1,%2,%3}, {%4,%5,%6,%7}, {%8,%9}, {%0,%1,%2,%3};"
        : "+f"(c[0]), "+f"(c[1]), "+f"(c[2]), "+f"(c[3])
        : "r"(a0), "r"(a1), "r"(a2), "r"(a3), "r"(b0), "r"(b1));
}

// ---------------- ChebConv combine GEMM (tf32 tensor cores) ----------------
// Y = relu([A0|Tx1|Tx2] @ W + b). Block: 128 nodes x 64 cols, K=192 (6x32).
// 8 warps; warp wm owns rows wm*16..+15, all 64 cols (8 n-tiles), via
// mma.m16n8k8. SMEM pads chosen for conflict-free fragment loads:
//   sA pitch 36 (bank = 4*gid + tig), sB pitch 72 (bank = 8*tig + gid).
#define A_P 36
#define B_P 72
template <int LAYER>
__global__ void __launch_bounds__(256)
k_gemm(const float* __restrict__ xp, const float* __restrict__ W,
       const float* __restrict__ bias) {
    __shared__ uint32_t sA[128 * A_P];     // 18432 B
    __shared__ uint32_t sB[32 * B_P];      //  9216 B

    const float* A0 = (LAYER == 0) ? xp : g_H;
    int t = threadIdx.x;
    int lane = t & 31, wm = t >> 5;        // warp 0..7
    int gid = lane >> 2, tig = lane & 3;   // octet row / quad col
    int nbase = blockIdx.x * 128;

    float acc[8][4];
#pragma unroll
    for (int nt = 0; nt < 8; nt++) {
        float b0 = __ldg(&bias[nt * 8 + 2 * tig]);
        float b1 = __ldg(&bias[nt * 8 + 2 * tig + 1]);
        acc[nt][0] = b0; acc[nt][1] = b1; acc[nt][2] = b0; acc[nt][3] = b1;
    }

#pragma unroll 1
    for (int chunk = 0; chunk < 6; chunk++) {
        int term = chunk >> 1;
        int ch0 = (chunk & 1) * 32;
        const float* A = (term == 0) ? A0 : ((term == 1) ? g_Tx1 : g_Tx2);

        // stage A tile: 128 nodes x 32 channels (tf32-converted)
#pragma unroll
        for (int i = t; i < 1024; i += 256) {
            int nn = i >> 3, q = i & 7;
            int node = nbase + nn;
            float4 v = make_float4(0.f, 0.f, 0.f, 0.f);
            if (node < NN)
                v = *(const float4*)&A[(size_t)node * NCH + ch0 + q * 4];
            uint32_t* p = &sA[nn * A_P + q * 4];
            p[0] = f2tf(v.x); p[1] = f2tf(v.y);
            p[2] = f2tf(v.z); p[3] = f2tf(v.w);
        }
        // stage B tile: W rows chunk*32..+31, 64 cols
#pragma unroll
        for (int i = t; i < 512; i += 256) {
            int r = i >> 4, qc = (i & 15) * 4;
            float4 v = *(const float4*)&W[(chunk * 32 + r) * 64 + qc];
            uint32_t* p = &sB[r * B_P + qc];
            p[0] = f2tf(v.x); p[1] = f2tf(v.y);
            p[2] = f2tf(v.z); p[3] = f2tf(v.w);
        }
        __syncthreads();

#pragma unroll
        for (int ks = 0; ks < 4; ks++) {
            int k0 = ks * 8;
            int row0 = wm * 16 + gid;
            uint32_t a0 = sA[row0 * A_P + k0 + tig];
            uint32_t a1 = sA[(row0 + 8) * A_P + k0 + tig];
            uint32_t a2 = sA[row0 * A_P + k0 + tig + 4];
            uint32_t a3 = sA[(row0 + 8) * A_P + k0 + tig + 4];
#pragma unroll
            for (int nt = 0; nt < 8; nt++) {
                uint32_t b0 = sB[(k0 + tig) * B_P + nt * 8 + gid];
                uint32_t b1 = sB[(k0 + tig + 4) * B_P + nt * 8 + gid];
                mma_tf32(acc[nt], a0, a1, a2, a3, b0, b1);
            }
        }
        __syncthreads();
    }

    // writeback with relu. c0,c1 -> row gid, cols 2tig,2tig+1; c2,c3 -> row gid+8
    int nr0 = nbase + wm * 16 + gid;
    int nr1 = nr0 + 8;
#pragma unroll
    for (int nt = 0; nt < 8; nt++) {
        int col = nt * 8 + 2 * tig;
        if (nr0 < NN) {
            float2 o;
            o.x = fmaxf(acc[nt][0], 0.f);
            o.y = fmaxf(acc[nt][1], 0.f);
            *(float2*)&g_Y[(size_t)nr0 * NCH + col] = o;
        }
        if (nr1 < NN) {
            float2 o;
            o.x = fmaxf(acc[nt][2], 0.f);
            o.y = fmaxf(acc[nt][3], 0.f);
            *(float2*)&g_Y[(size_t)nr1 * NCH + col] = o;
        }
    }
}

// ---------------- InstanceNorm: deterministic two-level reduction ----------
__global__ void k_stats1() {
    int c = threadIdx.x & 63;
    int r = threadIdx.x >> 6;   // 0..3
    float s = 0.f, ss = 0.f;
    for (int node = blockIdx.x * 4 + r; node < NN; node += SBLK * 4) {
        float v = g_Y[(size_t)node * NCH + c];
        s += v; ss += v * v;
    }
    __shared__ float sh[2][256];
    sh[0][threadIdx.x] = s;
    sh[1][threadIdx.x] = ss;
    __syncthreads();
    if (threadIdx.x < 64) {
        float S  = sh[0][c] + sh[0][c + 64] + sh[0][c + 128] + sh[0][c + 192];
        float SS = sh[1][c] + sh[1][c + 64] + sh[1][c + 128] + sh[1][c + 192];
        g_part[blockIdx.x * 64 + c] = S;
        g_part[(SBLK + blockIdx.x) * 64 + c] = SS;
    }
}

__global__ void k_stats2() {
    int c = threadIdx.x;
    if (c < 64) {
        float S = 0.f, SS = 0.f;
        for (int b = 0; b < SBLK; b++) {
            S += g_part[b * 64 + c];
            SS += g_part[(SBLK + b) * 64 + c];
        }
        float m = S / (float)NN;
        float var = SS / (float)NN - m * m;
        g_stats[c] = m;
        g_stats[64 + c] = rsqrtf(var + EPS);
    }
}

// LAYER 0: write g_H; LAYER 1: write outp
template <int LAYER>
__global__ void k_norm(float* __restrict__ outp) {
    float* O = (LAYER == 0) ? g_H : outp;
    __shared__ float sm_m[64], sm_r[64];
    if (threadIdx.x < 64) {
        sm_m[threadIdx.x] = g_stats[threadIdx.x];
        sm_r[threadIdx.x] = g_stats[64 + threadIdx.x];
    }
    __syncthreads();
    int i = blockIdx.x * blockDim.x + threadIdx.x;   // over float4 elements
    int total = NN * (NCH / 4);
    if (i < total) {
        float4 v = ((const float4*)g_Y)[i];
        int q = (i & 15) * 4;
        float4 o;
        o.x = (v.x - sm_m[q + 0]) * sm_r[q + 0];
        o.y = (v.y - sm_m[q + 1]) * sm_r[q + 1];
        o.z = (v.z - sm_m[q + 2]) * sm_r[q + 2];
        o.w = (v.w - sm_m[q + 3]) * sm_r[q + 3];
        ((float4*)O)[i] = o;
    }
}

// ---------------- launch (kernel launches ONLY — no other CUDA APIs) -------
extern "C" void kernel_launch(void* const* d_in, const int* in_sizes, int n_in,
                              void* d_out, int out_size) {
    const float* x        = (const float*)d_in[0];
    const int* ei         = (const int*)d_in[1];
    const float* W1       = (const float*)d_in[2];
    const float* b1       = (const float*)d_in[3];
    const float* W2       = (const float*)d_in[4];
    const float* b2       = (const float*)d_in[5];
    float* out            = (float*)d_out;

    const int TB = 256;
    int nodeBlocks = (NN + TB - 1) / TB;
    int edgeBlocks = (NE + TB - 1) / TB;
    int propBlocks = (NN + 7) / 8;            // 8 warps/block, 1 node/warp
    int gemmBlocks = (NN + 127) / 128;
    int normBlocks = (NN * 16 + TB - 1) / TB;

    // ----- graph structure build (per launch) -----
    k_zero_deg<<<nodeBlocks, TB>>>();
    k_deg<<<edgeBlocks, TB>>>(ei);
    k_dinv<<<nodeBlocks, TB>>>();
    k_scan1<<<NB1, SCAN_BLK>>>();
    k_scan2<<<1, 32>>>();
    k_scan3<<<(NN + TB - 1) / TB, TB>>>();
    k_curinit<<<nodeBlocks, TB>>>();
    k_fill<<<edgeBlocks, TB>>>(ei);

    // ----- layer 1 -----
    k_prop<0><<<propBlocks, TB>>>(x);
    k_prop<1><<<propBlocks, TB>>>(x);
    k_gemm<0><<<gemmBlocks, 256>>>(x, W1, b1);
    k_stats1<<<SBLK, 256>>>();
    k_stats2<<<1, 64>>>();
    k_norm<0><<<normBlocks, TB>>>(out);

    // ----- layer 2 -----
    k_prop<2><<<propBlocks, TB>>>(x);
    k_prop<3><<<propBlocks, TB>>>(x);
    k_gemm<1><<<gemmBlocks, 256>>>(x, W2, b2);
    k_stats1<<<SBLK, 256>>>();
    k_stats2<<<1, 64>>>();
    k_norm<1><<<normBlocks, TB>>>(out);
}

// round 5
// speedup vs baseline: 1.3972x; 1.0185x over previous
#include <cuda_runtime.h>
#include <cstdint>

#define NN 100000
#define NE 1600000
#define NCH 64
#define EPS 1e-5f
#define SCAN_BLK 1024
#define NB1 ((NN + SCAN_BLK - 1) / SCAN_BLK)   // 98
#define GB  ((NN + 127) / 128)                 // 782 gemm blocks

// ---------------- scratch (device globals; no allocation allowed) ----------
__device__ int   g_deg[NN];
__device__ float g_dinv[NN];
__device__ int   g_off[NN + 1];
__device__ int   g_cur[NN];
__device__ int   g_bsum[NB1];
__device__ int2  g_csr[NE];                    // {src, w bits}
__device__ float g_Tx1[(size_t)NN * NCH];
__device__ float g_Tx2[(size_t)NN * NCH];
__device__ float g_H[(size_t)NN * NCH];
__device__ float g_Y[(size_t)NN * NCH];
__device__ float g_part[2 * GB * NCH];
__device__ float g_stats[2 * NCH];

// ---------------- degree ---------------------------------------------------
__global__ void k_zero_deg() {
    int i = blockIdx.x * blockDim.x + threadIdx.x;
    if (i < NN) g_deg[i] = 0;
}

// edge_index is int32 (JAX default x64-disabled demotes int64 -> int32)
// 4 dst indices per thread via int4.
__global__ void k_deg(const int* __restrict__ ei) {
    int i = blockIdx.x * blockDim.x + threadIdx.x;
    if (i < NE / 4) {
        int4 d = ((const int4*)(ei + NE))[i];
        if ((unsigned)d.x < NN) atomicAdd(&g_deg[d.x], 1);
        if ((unsigned)d.y < NN) atomicAdd(&g_deg[d.y], 1);
        if ((unsigned)d.z < NN) atomicAdd(&g_deg[d.z], 1);
        if ((unsigned)d.w < NN) atomicAdd(&g_deg[d.w], 1);
    }
}

// ---------------- prefix sum (3-phase), dinv fused into phase 1 ------------
__global__ void k_scan1() {
    __shared__ int sh[SCAN_BLK];
    int tid = threadIdx.x;
    int i = blockIdx.x * SCAN_BLK + tid;
    int v = 0;
    if (i < NN) {
        v = g_deg[i];
        g_dinv[i] = (v > 0) ? rsqrtf((float)v) : 0.0f;
    }
    sh[tid] = v;
    __syncthreads();
    for (int ofs = 1; ofs < SCAN_BLK; ofs <<= 1) {
        int t = (tid >= ofs) ? sh[tid - ofs] : 0;
        __syncthreads();
        sh[tid] += t;
        __syncthreads();
    }
    if (i < NN) g_off[i + 1] = sh[tid];       // local inclusive
    if (tid == SCAN_BLK - 1) g_bsum[blockIdx.x] = sh[tid];
}

__global__ void k_scan2() {
    if (threadIdx.x == 0 && blockIdx.x == 0) {
        int a = 0;
        for (int b = 0; b < NB1; b++) { int t = g_bsum[b]; g_bsum[b] = a; a += t; }
    }
}

// phase 3 + cur init fused: final off[i+1] is also cur[i+1]
__global__ void k_scan3() {
    int i = blockIdx.x * blockDim.x + threadIdx.x;
    if (i < NN) {
        int fin = g_off[i + 1] + g_bsum[i / SCAN_BLK];
        g_off[i + 1] = fin;
        if (i + 1 < NN) g_cur[i + 1] = fin;
    }
    if (i == 0) { g_off[0] = 0; g_cur[0] = 0; }
}

// ---------------- counting-sort edges into CSR by dst ----------------------
__global__ void k_fill(const int* __restrict__ ei) {
    int e = blockIdx.x * blockDim.x + threadIdx.x;
    if (e < NE) {
        int s = ei[e];
        int d = ei[NE + e];
        if ((unsigned)s < NN && (unsigned)d < NN) {
            float w = -g_dinv[s] * g_dinv[d];
            int pos = atomicAdd(&g_cur[d], 1);
            if ((unsigned)pos < NE)
                g_csr[pos] = make_int2(s, __float_as_int(w));
        }
    }
}

// ---------------- sparse propagation: one warp per dst node ----------------
// Half-warp per edge: lanes 0-15 take even edge, 16-31 odd. Each lane covers
// 16B (float4) of the 256B row; halves combined via shfl.
// MODE 0: h=xp,    o=g_Tx1            MODE 1: h=g_Tx1, o=g_Tx2, sub=xp
// MODE 2: h=g_H,   o=g_Tx1            MODE 3: h=g_Tx1, o=g_Tx2, sub=g_H
template <int MODE>
__global__ void k_prop(const float* __restrict__ xp) {
    const float* h;
    float* o;
    const float* sub = nullptr;
    if (MODE == 0) { h = xp;    o = g_Tx1; }
    if (MODE == 1) { h = g_Tx1; o = g_Tx2; sub = xp; }
    if (MODE == 2) { h = g_H;   o = g_Tx1; }
    if (MODE == 3) { h = g_Tx1; o = g_Tx2; sub = g_H; }

    int node = blockIdx.x * (blockDim.x >> 5) + (threadIdx.x >> 5);
    if (node >= NN) return;
    int lane = threadIdx.x & 31;
    int half = lane >> 4;           // 0 or 1
    int q4 = (lane & 15) * 4;       // column offset (floats)
    int beg = g_off[node], end = g_off[node + 1];

    float4 acc = make_float4(0.f, 0.f, 0.f, 0.f);
    int j = beg;
    // 8 edges per iteration (4 per half-warp) for MLP
    for (; j + 7 < end; j += 8) {
        int2 ea = g_csr[j + half];
        int2 eb = g_csr[j + 2 + half];
        int2 ec = g_csr[j + 4 + half];
        int2 ed = g_csr[j + 6 + half];
        const float4 va = *(const float4*)(h + (size_t)ea.x * NCH + q4);
        const float4 vb = *(const float4*)(h + (size_t)eb.x * NCH + q4);
        const float4 vc = *(const float4*)(h + (size_t)ec.x * NCH + q4);
        const float4 vd = *(const float4*)(h + (size_t)ed.x * NCH + q4);
        float wa = __int_as_float(ea.y), wb = __int_as_float(eb.y);
        float wc = __int_as_float(ec.y), wd = __int_as_float(ed.y);
        acc.x += wa * va.x + wb * vb.x + wc * vc.x + wd * vd.x;
        acc.y += wa * va.y + wb * vb.y + wc * vc.y + wd * vd.y;
        acc.z += wa * va.z + wb * vb.z + wc * vc.z + wd * vd.z;
        acc.w += wa * va.w + wb * vb.w + wc * vc.w + wd * vd.w;
    }
    for (; j + 3 < end; j += 4) {
        int2 ea = g_csr[j + half];
        int2 eb = g_csr[j + 2 + half];
        const float4 va = *(const float4*)(h + (size_t)ea.x * NCH + q4);
        const float4 vb = *(const float4*)(h + (size_t)eb.x * NCH + q4);
        float wa = __int_as_float(ea.y), wb = __int_as_float(eb.y);
        acc.x += wa * va.x + wb * vb.x;
        acc.y += wa * va.y + wb * vb.y;
        acc.z += wa * va.z + wb * vb.z;
        acc.w += wa * va.w + wb * vb.w;
    }
    for (; j < end; j += 2) {
        int jj = j + half;
        int s = 0; float w = 0.f;
        if (jj < end) { int2 e = g_csr[jj]; s = e.x; w = __int_as_float(e.y); }
        const float4 v = *(const float4*)(h + (size_t)s * NCH + q4);
        acc.x += w * v.x; acc.y += w * v.y;
        acc.z += w * v.z; acc.w += w * v.w;
    }
    acc.x += __shfl_xor_sync(0xffffffffu, acc.x, 16);
    acc.y += __shfl_xor_sync(0xffffffffu, acc.y, 16);
    acc.z += __shfl_xor_sync(0xffffffffu, acc.z, 16);
    acc.w += __shfl_xor_sync(0xffffffffu, acc.w, 16);

    if (half == 0) {
        float4 r;
        if (MODE == 1 || MODE == 3) {
            float4 s = *(const float4*)(sub + (size_t)node * NCH + q4);
            r.x = 2.0f * acc.x - s.x;
            r.y = 2.0f * acc.y - s.y;
            r.z = 2.0f * acc.z - s.z;
            r.w = 2.0f * acc.w - s.w;
        } else {
            r = acc;
        }
        *(float4*)(o + (size_t)node * NCH + q4) = r;
    }
}

// ---------------- tf32 helpers ---------------------------------------------
__device__ __forceinline__ uint32_t f2tf(float x) {
    uint32_t r;
    asm("cvt.rna.tf32.f32 %0, %1;" : "=r"(r) : "f"(x));
    return r;
}

__device__ __forceinline__ void mma_tf32(float* c, uint32_t a0, uint32_t a1,
                                         uint32_t a2, uint32_t a3,
                                         uint32_t b0, uint32_t b1) {
    asm volatile(
        "mma.sync.aligned.m16n8k8.row.col.f32.tf32.tf32.f32 "
        "{%0,%1,%2,%3}, {%4,%5,%6,%7}, {%8,%9}, {%0,%1,%2,%3};"
        : "+f"(c[0]), "+f"(c[1]), "+f"(c[2]), "+f"(c[3])
        : "r"(a0), "r"(a1), "r"(a2), "r"(a3), "r"(b0), "r"(b1));
}

// ---------------- ChebConv GEMM (tf32) + fused relu-stats ------------------
// Y = relu([A0|Tx1|Tx2] @ W + b). Block: 128 nodes x 64 cols, K=192 (6x32).
// Epilogue: deterministic per-block channel sum/sumsq -> g_part.
#define A_P 36
#define B_P 72
template <int LAYER>
__global__ void __launch_bounds__(256)
k_gemm(const float* __restrict__ xp, const float* __restrict__ W,
       const float* __restrict__ bias) {
    __shared__ uint32_t sA[128 * A_P];     // 18432 B
    __shared__ uint32_t sB[32 * B_P];      //  9216 B

    const float* A0 = (LAYER == 0) ? xp : g_H;
    int t = threadIdx.x;
    int lane = t & 31, wm = t >> 5;        // warp 0..7
    int gid = lane >> 2, tig = lane & 3;   // octet row / quad col
    int nbase = blockIdx.x * 128;

    float acc[8][4];
#pragma unroll
    for (int nt = 0; nt < 8; nt++) {
        float b0 = __ldg(&bias[nt * 8 + 2 * tig]);
        float b1 = __ldg(&bias[nt * 8 + 2 * tig + 1]);
        acc[nt][0] = b0; acc[nt][1] = b1; acc[nt][2] = b0; acc[nt][3] = b1;
    }

#pragma unroll 1
    for (int chunk = 0; chunk < 6; chunk++) {
        int term = chunk >> 1;
        int ch0 = (chunk & 1) * 32;
        const float* A = (term == 0) ? A0 : ((term == 1) ? g_Tx1 : g_Tx2);

#pragma unroll
        for (int i = t; i < 1024; i += 256) {
            int nn = i >> 3, q = i & 7;
            int node = nbase + nn;
            float4 v = make_float4(0.f, 0.f, 0.f, 0.f);
            if (node < NN)
                v = *(const float4*)&A[(size_t)node * NCH + ch0 + q * 4];
            uint32_t* p = &sA[nn * A_P + q * 4];
            p[0] = f2tf(v.x); p[1] = f2tf(v.y);
            p[2] = f2tf(v.z); p[3] = f2tf(v.w);
        }
#pragma unroll
        for (int i = t; i < 512; i += 256) {
            int r = i >> 4, qc = (i & 15) * 4;
            float4 v = *(const float4*)&W[(chunk * 32 + r) * 64 + qc];
            uint32_t* p = &sB[r * B_P + qc];
            p[0] = f2tf(v.x); p[1] = f2tf(v.y);
            p[2] = f2tf(v.z); p[3] = f2tf(v.w);
        }
        __syncthreads();

#pragma unroll
        for (int ks = 0; ks < 4; ks++) {
            int k0 = ks * 8;
            int row0 = wm * 16 + gid;
            uint32_t a0 = sA[row0 * A_P + k0 + tig];
            uint32_t a1 = sA[(row0 + 8) * A_P + k0 + tig];
            uint32_t a2 = sA[row0 * A_P + k0 + tig + 4];
            uint32_t a3 = sA[(row0 + 8) * A_P + k0 + tig + 4];
#pragma unroll
            for (int nt = 0; nt < 8; nt++) {
                uint32_t b0 = sB[(k0 + tig) * B_P + nt * 8 + gid];
                uint32_t b1 = sB[(k0 + tig + 4) * B_P + nt * 8 + gid];
                mma_tf32(acc[nt], a0, a1, a2, a3, b0, b1);
            }
        }
        __syncthreads();
    }

    // relu + validity mask, writeback, keep values for stats
    int nr0 = nbase + wm * 16 + gid;
    int nr1 = nr0 + 8;
    bool ok0 = nr0 < NN, ok1 = nr1 < NN;
    float v0[8][2], v1[8][2];
#pragma unroll
    for (int nt = 0; nt < 8; nt++) {
        int col = nt * 8 + 2 * tig;
        v0[nt][0] = ok0 ? fmaxf(acc[nt][0], 0.f) : 0.f;
        v0[nt][1] = ok0 ? fmaxf(acc[nt][1], 0.f) : 0.f;
        v1[nt][0] = ok1 ? fmaxf(acc[nt][2], 0.f) : 0.f;
        v1[nt][1] = ok1 ? fmaxf(acc[nt][3], 0.f) : 0.f;
        if (ok0) *(float2*)&g_Y[(size_t)nr0 * NCH + col] =
                     make_float2(v0[nt][0], v0[nt][1]);
        if (ok1) *(float2*)&g_Y[(size_t)nr1 * NCH + col] =
                     make_float2(v1[nt][0], v1[nt][1]);
    }

    // ---- fused stats: deterministic block-level channel sums --------------
    float* sstage = (float*)sA;            // 64 x 65 floats = 16640 B
    float* ps = (float*)sB;                // 4*64 sums
    float* pq = ps + 256;                  // 4*64 sumsq
    int c_red = t & 63, grp = t >> 6;
    float locS = 0.f, locQ = 0.f;

#pragma unroll
    for (int p = 0; p < 2; p++) {          // halves: rows 0-63, 64-127
        __syncthreads();
        if ((wm >> 2) == p) {
            int rl0 = (wm & 3) * 16 + gid; // 0..63 local row
#pragma unroll
            for (int nt = 0; nt < 8; nt++) {
                int col = nt * 8 + 2 * tig;
                sstage[rl0 * 65 + col]           = v0[nt][0];
                sstage[rl0 * 65 + col + 1]       = v0[nt][1];
                sstage[(rl0 + 8) * 65 + col]     = v1[nt][0];
                sstage[(rl0 + 8) * 65 + col + 1] = v1[nt][1];
            }
        }
        __syncthreads();
#pragma unroll
        for (int rr = 0; rr < 16; rr++) {
            float v = sstage[(grp * 16 + rr) * 65 + c_red];
            locS += v; locQ += v * v;
        }
    }
    __syncthreads();
    ps[grp * 64 + c_red] = locS;
    pq[grp * 64 + c_red] = locQ;
    __syncthreads();
    if (t < 64) {
        float S = ps[t] + ps[64 + t] + ps[128 + t] + ps[192 + t];
        float Q = pq[t] + pq[64 + t] + pq[128 + t] + pq[192 + t];
        g_part[blockIdx.x * 64 + t] = S;
        g_part[(GB + blockIdx.x) * 64 + t] = Q;
    }
}

// ---------------- stats finalize -------------------------------------------
__global__ void k_stats2() {
    __shared__ float sh[2][256];
    int c = threadIdx.x & 63, r = threadIdx.x >> 6;
    float S = 0.f, Q = 0.f;
    for (int b = r; b < GB; b += 4) {
        S += g_part[b * 64 + c];
        Q += g_part[(GB + b) * 64 + c];
    }
    sh[0][threadIdx.x] = S;
    sh[1][threadIdx.x] = Q;
    __syncthreads();
    if (threadIdx.x < 64) {
        float Sf = sh[0][c] + sh[0][c + 64] + sh[0][c + 128] + sh[0][c + 192];
        float Qf = sh[1][c] + sh[1][c + 64] + sh[1][c + 128] + sh[1][c + 192];
        float m = Sf / (float)NN;
        float var = Qf / (float)NN - m * m;
        g_stats[c] = m;
        g_stats[64 + c] = rsqrtf(var + EPS);
    }
}

// LAYER 0: write g_H; LAYER 1: write outp
template <int LAYER>
__global__ void k_norm(float* __restrict__ outp) {
    float* O = (LAYER == 0) ? g_H : outp;
    __shared__ float sm_m[64], sm_r[64];
    if (threadIdx.x < 64) {
        sm_m[threadIdx.x] = g_stats[threadIdx.x];
        sm_r[threadIdx.x] = g_stats[64 + threadIdx.x];
    }
    __syncthreads();
    int i = blockIdx.x * blockDim.x + threadIdx.x;   // over float4 elements
    int total = NN * (NCH / 4);
    if (i < total) {
        float4 v = ((const float4*)g_Y)[i];
        int q = (i & 15) * 4;
        float4 o;
        o.x = (v.x - sm_m[q + 0]) * sm_r[q + 0];
        o.y = (v.y - sm_m[q + 1]) * sm_r[q + 1];
        o.z = (v.z - sm_m[q + 2]) * sm_r[q + 2];
        o.w = (v.w - sm_m[q + 3]) * sm_r[q + 3];
        ((float4*)O)[i] = o;
    }
}

// ---------------- launch (kernel launches ONLY — no other CUDA APIs) -------
extern "C" void kernel_launch(void* const* d_in, const int* in_sizes, int n_in,
                              void* d_out, int out_size) {
    const float* x        = (const float*)d_in[0];
    const int* ei         = (const int*)d_in[1];
    const float* W1       = (const float*)d_in[2];
    const float* b1       = (const float*)d_in[3];
    const float* W2       = (const float*)d_in[4];
    const float* b2       = (const float*)d_in[5];
    float* out            = (float*)d_out;

    const int TB = 256;
    int nodeBlocks = (NN + TB - 1) / TB;
    int edgeBlocks = (NE + TB - 1) / TB;
    int edge4Blocks = (NE / 4 + TB - 1) / TB;
    int propBlocks = (NN + 7) / 8;            // 8 warps/block, 1 node/warp
    int normBlocks = (NN * 16 + TB - 1) / TB;

    // ----- graph structure build (per launch) -----
    k_zero_deg<<<nodeBlocks, TB>>>();
    k_deg<<<edge4Blocks, TB>>>(ei);
    k_scan1<<<NB1, SCAN_BLK>>>();
    k_scan2<<<1, 32>>>();
    k_scan3<<<(NN + TB - 1) / TB, TB>>>();
    k_fill<<<edgeBlocks, TB>>>(ei);

    // ----- layer 1 -----
    k_prop<0><<<propBlocks, TB>>>(x);
    k_prop<1><<<propBlocks, TB>>>(x);
    k_gemm<0><<<GB, 256>>>(x, W1, b1);
    k_stats2<<<1, 256>>>();
    k_norm<0><<<normBlocks, TB>>>(out);

    // ----- layer 2 -----
    k_prop<2><<<propBlocks, TB>>>(x);
    k_prop<3><<<propBlocks, TB>>>(x);
    k_gemm<1><<<GB, 256>>>(x, W2, b2);
    k_stats2<<<1, 256>>>();
    k_norm<1><<<normBlocks, TB>>>(out);
}